// round 2
// baseline (speedup 1.0000x reference)
#include <cuda_runtime.h>
#include <math.h>

#define N_NODES 100000
#define N_EDGES 600000
#define H 128
#define R 16
#define SCALING 2.0f
#define LN_EPS 1e-5f

#define SCAN_CHUNK 512
#define SCAN_NB ((N_NODES + SCAN_CHUNK - 1) / SCAN_CHUNK)   // 196

#define ROWS_PER_BLOCK 64
#define FUSED_THREADS 256
#define FUSED_SMEM ((2 * H * H + 2 * ROWS_PER_BLOCK * H) * (int)sizeof(float))  // 192 KB

// ---------- static device scratch (no allocation allowed) ----------
__device__ int   g_deg[N_NODES];
__device__ int   g_cursor[N_NODES];
__device__ int   g_off[N_NODES + 1];
__device__ float g_dinv[N_NODES];
__device__ int   g_srow[N_EDGES];
__device__ float g_m[N_NODES * H];          // aggregated messages (51.2 MB)
__device__ float g_weff[2 * H * H];         // WeffT[k*H+j], msg then gate
__device__ int   g_bsum[256];

// ---------- 1. zero counters ----------
__global__ void zero_kernel() {
    int i = blockIdx.x * blockDim.x + threadIdx.x;
    if (i < N_NODES) { g_deg[i] = 0; g_cursor[i] = 0; }
}

// ---------- 2. in-degree histogram (int atomics, cheap) ----------
__global__ void hist_kernel(const int* __restrict__ col) {
    int e = blockIdx.x * blockDim.x + threadIdx.x;
    if (e < N_EDGES) atomicAdd(&g_deg[col[e]], 1);
}

// ---------- 3. exclusive scan over degrees -> CSR offsets ----------
__global__ void scan_pass1() {
    __shared__ int sh[SCAN_CHUNK];
    int i = blockIdx.x * SCAN_CHUNK + threadIdx.x;
    sh[threadIdx.x] = (i < N_NODES) ? g_deg[i] : 0;
    __syncthreads();
    for (int off = SCAN_CHUNK / 2; off > 0; off >>= 1) {
        if (threadIdx.x < off) sh[threadIdx.x] += sh[threadIdx.x + off];
        __syncthreads();
    }
    if (threadIdx.x == 0) g_bsum[blockIdx.x] = sh[0];
}

__global__ void scan_pass2() {
    if (threadIdx.x == 0) {
        int s = 0;
        for (int b = 0; b < SCAN_NB; b++) { int t = g_bsum[b]; g_bsum[b] = s; s += t; }
        g_off[N_NODES] = s;  // == N_EDGES
    }
}

__global__ void scan_pass3() {
    __shared__ int sh[SCAN_CHUNK];
    int i = blockIdx.x * SCAN_CHUNK + threadIdx.x;
    int v = (i < N_NODES) ? g_deg[i] : 0;
    sh[threadIdx.x] = v;
    __syncthreads();
    for (int off = 1; off < SCAN_CHUNK; off <<= 1) {
        int t = (threadIdx.x >= off) ? sh[threadIdx.x - off] : 0;
        __syncthreads();
        sh[threadIdx.x] += t;
        __syncthreads();
    }
    if (i < N_NODES) g_off[i] = g_bsum[blockIdx.x] + sh[threadIdx.x] - v;
}

// ---------- 4. dinv = (deg_in + 1)^-0.5  (self loop included) ----------
__global__ void dinv_kernel() {
    int i = blockIdx.x * blockDim.x + threadIdx.x;
    if (i < N_NODES) g_dinv[i] = rsqrtf((float)(g_deg[i] + 1));
}

// ---------- 5. bucket edges by target (CSR column build) ----------
__global__ void scatter_kernel(const int* __restrict__ row,
                               const int* __restrict__ col) {
    int e = blockIdx.x * blockDim.x + threadIdx.x;
    if (e < N_EDGES) {
        int c = col[e];
        int pos = g_off[c] + atomicAdd(&g_cursor[c], 1);
        g_srow[pos] = row[e];
    }
}

// ---------- 6. gather-aggregate: 1 warp per node, no float atomics ----------
__global__ void gather_kernel(const float* __restrict__ x) {
    int warp = (blockIdx.x * blockDim.x + threadIdx.x) >> 5;
    int lane = threadIdx.x & 31;
    if (warp >= N_NODES) return;
    int c = warp;
    const float4* x4 = (const float4*)x;
    float4 acc = make_float4(0.f, 0.f, 0.f, 0.f);
    int beg = g_off[c], end = g_off[c + 1];
    for (int e = beg; e < end; e++) {
        int r = g_srow[e];
        float w = g_dinv[r];
        float4 v = x4[r * 32 + lane];
        acc.x += w * v.x; acc.y += w * v.y; acc.z += w * v.z; acc.w += w * v.w;
    }
    float dc   = g_dinv[c];
    float degt = (float)(end - beg + 1);            // in-degree + self loop
    float sc   = dc / degt;
    float4 xc  = x4[c * 32 + lane];
    float4 m;
    m.x = (acc.x + dc * xc.x) * sc;
    m.y = (acc.y + dc * xc.y) * sc;
    m.z = (acc.z + dc * xc.z) * sc;
    m.w = (acc.w + dc * xc.w) * sc;
    ((float4*)g_m)[c * 32 + lane] = m;
}

// ---------- 7. fold LoRA into effective weights: WeffT[k][j] = W[j][k] + s*sum_r B[j][r]A[r][k] ----------
__global__ void weff_kernel(const float* __restrict__ msg_W, const float* __restrict__ msg_A,
                            const float* __restrict__ msg_B,
                            const float* __restrict__ gate_W, const float* __restrict__ gate_A,
                            const float* __restrict__ gate_B) {
    int mat = blockIdx.x >> 7;       // 0 = msg, 1 = gate
    int k = blockIdx.x & 127;
    int j = threadIdx.x;
    const float* W = mat ? gate_W : msg_W;
    const float* A = mat ? gate_A : msg_A;
    const float* B = mat ? gate_B : msg_B;
    __shared__ float sa[R];
    if (j < R) sa[j] = A[j * H + k];
    __syncthreads();
    float acc = 0.f;
#pragma unroll
    for (int r = 0; r < R; r++) acc += B[j * R + r] * sa[r];
    g_weff[mat * H * H + k * H + j] = W[j * H + k] + SCALING * acc;
}

// ---------- 8. fused: two matvecs + sigmoid gate + residual + LayerNorm ----------
__global__ void __launch_bounds__(FUSED_THREADS, 1)
fused_kernel(const float* __restrict__ x,
             const float* __restrict__ msg_b, const float* __restrict__ gate_b,
             const float* __restrict__ ln_g, const float* __restrict__ ln_b,
             float* __restrict__ out) {
    extern __shared__ float smem[];
    float* sWm = smem;                       // [H*H] WeffT msg
    float* sWg = smem + H * H;               // [H*H] WeffT gate
    float* sM  = smem + 2 * H * H;           // [64*H] messages
    float* sH  = sM + ROWS_PER_BLOCK * H;    // [64*H] hidden

    int tid = threadIdx.x;
    const float4* w4   = (const float4*)g_weff;
    float4* sWm4 = (float4*)sWm;
    float4* sWg4 = (float4*)sWg;
#pragma unroll
    for (int i = 0; i < (H * H / 4) / FUSED_THREADS; i++) {  // 16 iters
        sWm4[tid + i * FUSED_THREADS] = w4[tid + i * FUSED_THREADS];
        sWg4[tid + i * FUSED_THREADS] = w4[H * H / 4 + tid + i * FUSED_THREADS];
    }

    int rowBase = blockIdx.x * ROWS_PER_BLOCK;
    const float4* x4 = (const float4*)x;
    const float4* m4 = (const float4*)g_m;
    float4* sM4 = (float4*)sM;
    float4* sH4 = (float4*)sH;
#pragma unroll
    for (int i = 0; i < (ROWS_PER_BLOCK * 32) / FUSED_THREADS; i++) {  // 8 iters
        int idx = tid + i * FUSED_THREADS;
        int row = rowBase + (idx >> 5);
        float4 zv = make_float4(0.f, 0.f, 0.f, 0.f);
        if (row < N_NODES) {
            sM4[idx] = m4[row * 32 + (idx & 31)];
            sH4[idx] = x4[row * 32 + (idx & 31)];
        } else { sM4[idx] = zv; sH4[idx] = zv; }
    }
    __syncthreads();

    int warp = tid >> 5, lane = tid & 31;
    int rloc = warp * 8;
    float4 am[8], ag[8];
#pragma unroll
    for (int r = 0; r < 8; r++) {
        am[r] = make_float4(0.f, 0.f, 0.f, 0.f);
        ag[r] = make_float4(0.f, 0.f, 0.f, 0.f);
    }

#pragma unroll 2
    for (int k = 0; k < H; k++) {
        float4 wm = sWm4[k * 32 + lane];
        float4 wg = sWg4[k * 32 + lane];
#pragma unroll
        for (int r = 0; r < 8; r++) {
            float mk = sM[(rloc + r) * H + k];
            float hk = sH[(rloc + r) * H + k];
            am[r].x += mk * wm.x; am[r].y += mk * wm.y; am[r].z += mk * wm.z; am[r].w += mk * wm.w;
            ag[r].x += hk * wg.x; ag[r].y += hk * wg.y; ag[r].z += hk * wg.z; ag[r].w += hk * wg.w;
        }
    }

    // epilogue: bias, sigmoid gate, residual, LayerNorm, store
    const float4 mb = ((const float4*)msg_b)[lane];
    const float4 gb = ((const float4*)gate_b)[lane];
    const float4 ga = ((const float4*)ln_g)[lane];
    const float4 be = ((const float4*)ln_b)[lane];
    float4* out4 = (float4*)out;

#pragma unroll
    for (int r = 0; r < 8; r++) {
        int row = rowBase + rloc + r;
        if (row >= N_NODES) break;
        float4 h = sH4[(rloc + r) * 32 + lane];
        float g0 = 1.f / (1.f + __expf(-(ag[r].x + gb.x)));
        float g1 = 1.f / (1.f + __expf(-(ag[r].y + gb.y)));
        float g2 = 1.f / (1.f + __expf(-(ag[r].z + gb.z)));
        float g3 = 1.f / (1.f + __expf(-(ag[r].w + gb.w)));
        float v0 = h.x + g0 * (am[r].x + mb.x);
        float v1 = h.y + g1 * (am[r].y + mb.y);
        float v2 = h.z + g2 * (am[r].z + mb.z);
        float v3 = h.w + g3 * (am[r].w + mb.w);
        float s  = v0 + v1 + v2 + v3;
        float s2 = v0 * v0 + v1 * v1 + v2 * v2 + v3 * v3;
#pragma unroll
        for (int off = 16; off > 0; off >>= 1) {
            s  += __shfl_xor_sync(0xffffffffu, s, off);
            s2 += __shfl_xor_sync(0xffffffffu, s2, off);
        }
        float mu   = s * (1.f / (float)H);
        float var  = s2 * (1.f / (float)H) - mu * mu;
        float rinv = rsqrtf(var + LN_EPS);
        float4 o;
        o.x = (v0 - mu) * rinv * ga.x + be.x;
        o.y = (v1 - mu) * rinv * ga.y + be.y;
        o.z = (v2 - mu) * rinv * ga.z + be.z;
        o.w = (v3 - mu) * rinv * ga.w + be.w;
        out4[row * 32 + lane] = o;
    }
}

// ---------- launch ----------
extern "C" void kernel_launch(void* const* d_in, const int* in_sizes, int n_in,
                              void* d_out, int out_size) {
    const float* x      = (const float*)d_in[0];
    const int*   ei     = (const int*)d_in[1];     // [2, E] int32 (JAX x64 disabled)
    const float* msg_W  = (const float*)d_in[2];
    const float* msg_b  = (const float*)d_in[3];
    const float* msg_A  = (const float*)d_in[4];
    const float* msg_B  = (const float*)d_in[5];
    const float* gate_W = (const float*)d_in[6];
    const float* gate_b = (const float*)d_in[7];
    const float* gate_A = (const float*)d_in[8];
    const float* gate_B = (const float*)d_in[9];
    const float* ln_g   = (const float*)d_in[10];
    const float* ln_b   = (const float*)d_in[11];
    float* out = (float*)d_out;

    const int* rows = ei;
    const int* cols = ei + N_EDGES;

    zero_kernel<<<(N_NODES + 255) / 256, 256>>>();
    hist_kernel<<<(N_EDGES + 255) / 256, 256>>>(cols);
    scan_pass1<<<SCAN_NB, SCAN_CHUNK>>>();
    scan_pass2<<<1, 32>>>();
    scan_pass3<<<SCAN_NB, SCAN_CHUNK>>>();
    dinv_kernel<<<(N_NODES + 255) / 256, 256>>>();
    scatter_kernel<<<(N_EDGES + 255) / 256, 256>>>(rows, cols);
    gather_kernel<<<(N_NODES * 32 + 255) / 256, 256>>>(x);
    weff_kernel<<<2 * H, H>>>(msg_W, msg_A, msg_B, gate_W, gate_A, gate_B);

    cudaFuncSetAttribute(fused_kernel, cudaFuncAttributeMaxDynamicSharedMemorySize, FUSED_SMEM);
    fused_kernel<<<(N_NODES + ROWS_PER_BLOCK - 1) / ROWS_PER_BLOCK, FUSED_THREADS, FUSED_SMEM>>>(
        x, msg_b, gate_b, ln_g, ln_b, out);
}

// round 3
// speedup vs baseline: 1.0276x; 1.0276x over previous
#include <cuda_runtime.h>
#include <math.h>

#define N_NODES 100000
#define N_EDGES 600000
#define H 128
#define R 16
#define SCALING 2.0f
#define LN_EPS 1e-5f

#define SCAN_CHUNK 512
#define SCAN_NB ((N_NODES + SCAN_CHUNK - 1) / SCAN_CHUNK)   // 196

#define TILE_ROWS 64
#define NTILES ((N_NODES + TILE_ROWS - 1) / TILE_ROWS)      // 1563
#define PAD_ROWS (NTILES * TILE_ROWS)                       // 100032
#define FUSED_THREADS 256
#define FUSED_GRID 148
// smem: weights 128*128 pairs (128KB) + rows 64*128 pairs (64KB) = 192KB
#define FUSED_SMEM ((H * H + TILE_ROWS * H) * 2 * (int)sizeof(float))

// ---------- static device scratch ----------
__device__ int    g_deg[N_NODES];
__device__ int    g_cursor[N_NODES];
__device__ int    g_off[N_NODES + 1];
__device__ float  g_dinv[N_NODES];
__device__ int    g_srow[N_EDGES];
__device__ float  g_mh[PAD_ROWS * 2 * H];    // (m,h) interleaved pairs, 102.4MB
__device__ float2 g_weffp[H * H];            // (Wmsg^T, Wgate^T) pairs [k*H+j]
__device__ int    g_bsum[256];

__device__ __forceinline__ void ffma2(unsigned long long& d,
                                      unsigned long long a,
                                      unsigned long long b) {
    asm("fma.rn.f32x2 %0, %1, %2, %0;" : "+l"(d) : "l"(a), "l"(b));
}
__device__ __forceinline__ float2 unpack2(unsigned long long v) {
    float2 r;
    asm("mov.b64 {%0, %1}, %2;" : "=f"(r.x), "=f"(r.y) : "l"(v));
    return r;
}

// ---------- 1. zero counters ----------
__global__ void zero_kernel() {
    int i = blockIdx.x * blockDim.x + threadIdx.x;
    if (i < N_NODES) { g_deg[i] = 0; g_cursor[i] = 0; }
}

// ---------- 2. in-degree histogram ----------
__global__ void hist_kernel(const int* __restrict__ col) {
    int e = blockIdx.x * blockDim.x + threadIdx.x;
    if (e < N_EDGES) atomicAdd(&g_deg[col[e]], 1);
}

// ---------- 3. scan ----------
__global__ void scan_pass1() {
    __shared__ int sh[SCAN_CHUNK];
    int i = blockIdx.x * SCAN_CHUNK + threadIdx.x;
    sh[threadIdx.x] = (i < N_NODES) ? g_deg[i] : 0;
    __syncthreads();
    for (int off = SCAN_CHUNK / 2; off > 0; off >>= 1) {
        if (threadIdx.x < off) sh[threadIdx.x] += sh[threadIdx.x + off];
        __syncthreads();
    }
    if (threadIdx.x == 0) g_bsum[blockIdx.x] = sh[0];
}

__global__ void scan_pass2() {       // parallel 256-wide scan over 196 sums
    __shared__ int sh[256];
    int t = threadIdx.x;
    int v = (t < SCAN_NB) ? g_bsum[t] : 0;
    sh[t] = v;
    __syncthreads();
    for (int off = 1; off < 256; off <<= 1) {
        int add = (t >= off) ? sh[t - off] : 0;
        __syncthreads();
        sh[t] += add;
        __syncthreads();
    }
    if (t < SCAN_NB) g_bsum[t] = sh[t] - v;   // exclusive
    if (t == 255) g_off[N_NODES] = sh[255];
}

__global__ void scan_pass3() {       // + dinv folded in
    __shared__ int sh[SCAN_CHUNK];
    int i = blockIdx.x * SCAN_CHUNK + threadIdx.x;
    int v = (i < N_NODES) ? g_deg[i] : 0;
    sh[threadIdx.x] = v;
    __syncthreads();
    for (int off = 1; off < SCAN_CHUNK; off <<= 1) {
        int t = (threadIdx.x >= off) ? sh[threadIdx.x - off] : 0;
        __syncthreads();
        sh[threadIdx.x] += t;
        __syncthreads();
    }
    if (i < N_NODES) {
        g_off[i]  = g_bsum[blockIdx.x] + sh[threadIdx.x] - v;
        g_dinv[i] = rsqrtf((float)(v + 1));
    }
}

// ---------- 5. bucket edges by target ----------
__global__ void scatter_kernel(const int* __restrict__ row,
                               const int* __restrict__ col) {
    int e = blockIdx.x * blockDim.x + threadIdx.x;
    if (e < N_EDGES) {
        int c = col[e];
        int pos = g_off[c] + atomicAdd(&g_cursor[c], 1);
        g_srow[pos] = row[e];
    }
}

// ---------- 6. gather-aggregate; writes (m,h) interleaved pairs ----------
__global__ void gather_kernel(const float* __restrict__ x) {
    int warp = (blockIdx.x * blockDim.x + threadIdx.x) >> 5;
    int lane = threadIdx.x & 31;
    if (warp >= N_NODES) return;
    int c = warp;
    const float4* x4 = (const float4*)x;
    float4 acc = make_float4(0.f, 0.f, 0.f, 0.f);
    int beg = g_off[c], end = g_off[c + 1];
    for (int e = beg; e < end; e++) {
        int r = g_srow[e];
        float w = g_dinv[r];
        float4 v = x4[r * 32 + lane];
        acc.x += w * v.x; acc.y += w * v.y; acc.z += w * v.z; acc.w += w * v.w;
    }
    float dc   = g_dinv[c];
    float degt = (float)(end - beg + 1);
    float sc   = dc / degt;
    float4 xc  = x4[c * 32 + lane];
    float m0 = (acc.x + dc * xc.x) * sc;
    float m1 = (acc.y + dc * xc.y) * sc;
    float m2 = (acc.z + dc * xc.z) * sc;
    float m3 = (acc.w + dc * xc.w) * sc;
    float4* dst = (float4*)(g_mh + (size_t)c * 2 * H);
    dst[lane * 2 + 0] = make_float4(m0, xc.x, m1, xc.y);
    dst[lane * 2 + 1] = make_float4(m2, xc.z, m3, xc.w);
}

// ---------- 7. effective weights as (msg,gate) pairs ----------
__global__ void weff_kernel(const float* __restrict__ msg_W, const float* __restrict__ msg_A,
                            const float* __restrict__ msg_B,
                            const float* __restrict__ gate_W, const float* __restrict__ gate_A,
                            const float* __restrict__ gate_B) {
    int k = blockIdx.x;          // 0..127
    int j = threadIdx.x;         // 0..127
    __shared__ float sam[R], sag[R];
    if (j < R) { sam[j] = msg_A[j * H + k]; sag[j] = gate_A[j * H + k]; }
    __syncthreads();
    float am = 0.f, ag = 0.f;
#pragma unroll
    for (int r = 0; r < R; r++) {
        am += msg_B[j * R + r] * sam[r];
        ag += gate_B[j * R + r] * sag[r];
    }
    g_weffp[k * H + j] = make_float2(msg_W[j * H + k] + SCALING * am,
                                     gate_W[j * H + k] + SCALING * ag);
}

// ---------- 8. persistent fused GEMM (f32x2 pair trick) + gate + LN ----------
__global__ void __launch_bounds__(FUSED_THREADS, 1)
fused_kernel(const float* __restrict__ msg_b, const float* __restrict__ gate_b,
             const float* __restrict__ ln_g, const float* __restrict__ ln_b,
             float* __restrict__ out) {
    extern __shared__ float smem[];
    float* sW   = smem;                 // H*H float2 pairs = 128KB
    float* sRow = smem + 2 * H * H;     // TILE_ROWS*H float2 pairs = 64KB

    int tid  = threadIdx.x;
    int warp = tid >> 5, lane = tid & 31;
    int rloc = warp * 8;

    // load weights once
    {
        const float4* wsrc = (const float4*)g_weffp;
        float4* wdst = (float4*)sW;
#pragma unroll
        for (int i = 0; i < 32; i++)                       // 8192 float4
            wdst[tid + i * 256] = wsrc[tid + i * 256];
    }

    // per-lane column constants (cols 2L,2L+1 and 64+2L,64+2L+1)
    const float2 mb_a = ((const float2*)msg_b)[lane];
    const float2 mb_b = ((const float2*)msg_b)[lane + 32];
    const float2 gb_a = ((const float2*)gate_b)[lane];
    const float2 gb_b = ((const float2*)gate_b)[lane + 32];
    const float2 ga_a = ((const float2*)ln_g)[lane];
    const float2 ga_b = ((const float2*)ln_g)[lane + 32];
    const float2 be_a = ((const float2*)ln_b)[lane];
    const float2 be_b = ((const float2*)ln_b)[lane + 32];

    const unsigned long long* sWp   = (const unsigned long long*)sW;
    const unsigned long long* sRowp = (const unsigned long long*)sRow;

    __syncthreads();

    for (int tile = blockIdx.x; tile < NTILES; tile += FUSED_GRID) {
        // stage 64 rows of (m,h) pairs: raw 64KB copy
        {
            const float4* src = (const float4*)(g_mh + (size_t)tile * TILE_ROWS * 2 * H);
            float4* dst = (float4*)sRow;
#pragma unroll
            for (int i = 0; i < 16; i++)                   // 4096 float4
                dst[tid + i * 256] = src[tid + i * 256];
        }
        __syncthreads();

        unsigned long long acc[8][4];
#pragma unroll
        for (int r = 0; r < 8; r++)
#pragma unroll
            for (int c = 0; c < 4; c++) acc[r][c] = 0ull;

#pragma unroll 4
        for (int k = 0; k < H; k++) {
            ulonglong2 wa = *(const ulonglong2*)(sWp + k * H + 2 * lane);       // cols 2L,2L+1
            ulonglong2 wb = *(const ulonglong2*)(sWp + k * H + 64 + 2 * lane);  // cols 64+2L..
#pragma unroll
            for (int r = 0; r < 8; r++) {
                unsigned long long rp = sRowp[(rloc + r) * H + k];   // (m,h) broadcast
                ffma2(acc[r][0], rp, wa.x);
                ffma2(acc[r][1], rp, wa.y);
                ffma2(acc[r][2], rp, wb.x);
                ffma2(acc[r][3], rp, wb.y);
            }
        }

        // epilogue
#pragma unroll
        for (int r = 0; r < 8; r++) {
            int row = tile * TILE_ROWS + rloc + r;
            float2 a0 = unpack2(acc[r][0]);   // (msg, gate_pre) col 2L
            float2 a1 = unpack2(acc[r][1]);   // col 2L+1
            float2 a2 = unpack2(acc[r][2]);   // col 64+2L
            float2 a3 = unpack2(acc[r][3]);   // col 64+2L+1
            float4 hp0 = *(const float4*)(sRowp + (rloc + r) * H + 2 * lane);
            float4 hp1 = *(const float4*)(sRowp + (rloc + r) * H + 64 + 2 * lane);
            float g0 = 1.f / (1.f + __expf(-(a0.y + gb_a.x)));
            float g1 = 1.f / (1.f + __expf(-(a1.y + gb_a.y)));
            float g2 = 1.f / (1.f + __expf(-(a2.y + gb_b.x)));
            float g3 = 1.f / (1.f + __expf(-(a3.y + gb_b.y)));
            float v0 = hp0.y + g0 * (a0.x + mb_a.x);
            float v1 = hp0.w + g1 * (a1.x + mb_a.y);
            float v2 = hp1.y + g2 * (a2.x + mb_b.x);
            float v3 = hp1.w + g3 * (a3.x + mb_b.y);
            float s  = v0 + v1 + v2 + v3;
            float s2 = v0 * v0 + v1 * v1 + v2 * v2 + v3 * v3;
#pragma unroll
            for (int off = 16; off > 0; off >>= 1) {
                s  += __shfl_xor_sync(0xffffffffu, s, off);
                s2 += __shfl_xor_sync(0xffffffffu, s2, off);
            }
            float mu   = s * (1.f / (float)H);
            float var  = s2 * (1.f / (float)H) - mu * mu;
            float rinv = rsqrtf(var + LN_EPS);
            if (row < N_NODES) {
                float2 oa, ob;
                oa.x = (v0 - mu) * rinv * ga_a.x + be_a.x;
                oa.y = (v1 - mu) * rinv * ga_a.y + be_a.y;
                ob.x = (v2 - mu) * rinv * ga_b.x + be_b.x;
                ob.y = (v3 - mu) * rinv * ga_b.y + be_b.y;
                float2* o2 = (float2*)(out + (size_t)row * H);
                o2[lane]      = oa;
                o2[lane + 32] = ob;
            }
        }
        __syncthreads();   // buffer reuse safety
    }
}

// ---------- launch ----------
extern "C" void kernel_launch(void* const* d_in, const int* in_sizes, int n_in,
                              void* d_out, int out_size) {
    const float* x      = (const float*)d_in[0];
    const int*   ei     = (const int*)d_in[1];
    const float* msg_W  = (const float*)d_in[2];
    const float* msg_b  = (const float*)d_in[3];
    const float* msg_A  = (const float*)d_in[4];
    const float* msg_B  = (const float*)d_in[5];
    const float* gate_W = (const float*)d_in[6];
    const float* gate_b = (const float*)d_in[7];
    const float* gate_A = (const float*)d_in[8];
    const float* gate_B = (const float*)d_in[9];
    const float* ln_g   = (const float*)d_in[10];
    const float* ln_b   = (const float*)d_in[11];
    float* out = (float*)d_out;

    const int* rows = ei;
    const int* cols = ei + N_EDGES;

    zero_kernel<<<(N_NODES + 255) / 256, 256>>>();
    hist_kernel<<<(N_EDGES + 255) / 256, 256>>>(cols);
    scan_pass1<<<SCAN_NB, SCAN_CHUNK>>>();
    scan_pass2<<<1, 256>>>();
    scan_pass3<<<SCAN_NB, SCAN_CHUNK>>>();
    scatter_kernel<<<(N_EDGES + 255) / 256, 256>>>(rows, cols);
    gather_kernel<<<(N_NODES * 32 + 255) / 256, 256>>>(x);
    weff_kernel<<<H, H>>>(msg_W, msg_A, msg_B, gate_W, gate_A, gate_B);

    cudaFuncSetAttribute(fused_kernel, cudaFuncAttributeMaxDynamicSharedMemorySize, FUSED_SMEM);
    fused_kernel<<<FUSED_GRID, FUSED_THREADS, FUSED_SMEM>>>(msg_b, gate_b, ln_g, ln_b, out);
}

// round 5
// speedup vs baseline: 1.2498x; 1.2162x over previous
#include <cuda_runtime.h>
#include <cuda_bf16.h>
#include <math.h>
#include <stdint.h>

#define N_NODES 100000
#define N_EDGES 600000
#define H 128
#define R 16
#define SCALING 2.0f
#define LN_EPS 1e-5f

#define SCAN_CHUNK 512
#define SCAN_NB ((N_NODES + SCAN_CHUNK - 1) / SCAN_CHUNK)   // 196

#define TILE_M 128
#define NT_TILES ((N_NODES + TILE_M - 1) / TILE_M)          // 782
#define FGRID 148
#define FTHREADS 256

// fused smem layout (bytes)
#define SMB_W    0                    // B-fragment images 128KB
#define SMB_MB   131072
#define SMB_GB   131584
#define SMB_GA   132096
#define SMB_BE   132608
#define SMB_S1   133120               // [2][128] f32
#define SMB_S2   134144
#define FUSED_SMEM 135168

// gather staging smem: 4 variants x (8 q * 516 padded words) u32
#define GQ_PAD 516
#define GATHER_SMEM (4 * 8 * GQ_PAD * 4)   // 66048 B

// ---------- static device scratch ----------
__device__ int   g_deg[N_NODES];
__device__ int   g_cursor[N_NODES];
__device__ int   g_off[N_NODES + 1];
__device__ float g_dinv[N_NODES];
__device__ int   g_srow[N_EDGES];
__device__ int   g_bsum[256];
// A fragments: [tile][q 8][mt 8][v 4][T 32] uint4 (a0..a3)   = 102.5 MB
__device__ uint4 g_afrag[(size_t)NT_TILES * 8 * 8 * 4 * 32];
// B fragments: [v 4][q 8][nt 16][T 32][b0,b1] u32 = 128 KB
__device__ unsigned g_wfrag[4 * 8 * 16 * 32 * 2];

// ---------- helpers ----------
__device__ __forceinline__ unsigned pack_bf2(float e0, float e1) {
    unsigned r;
    asm("cvt.rn.bf16x2.f32 %0, %1, %2;" : "=r"(r) : "f"(e1), "f"(e0));  // lo=e0, hi=e1
    return r;
}
__device__ __forceinline__ uint2 split_bf2(float e0, float e1) {
    unsigned hi = pack_bf2(e0, e1);
    float h0 = __uint_as_float(hi << 16);
    float h1 = __uint_as_float(hi & 0xffff0000u);
    unsigned lo = pack_bf2(e0 - h0, e1 - h1);
    return make_uint2(hi, lo);
}
__device__ __forceinline__ void mma16816(float* d, const unsigned* a, const unsigned* b) {
    asm volatile(
        "mma.sync.aligned.m16n8k16.row.col.f32.bf16.bf16.f32 "
        "{%0,%1,%2,%3}, {%4,%5,%6,%7}, {%8,%9}, {%0,%1,%2,%3};"
        : "+f"(d[0]), "+f"(d[1]), "+f"(d[2]), "+f"(d[3])
        : "r"(a[0]), "r"(a[1]), "r"(a[2]), "r"(a[3]), "r"(b[0]), "r"(b[1]));
}

// ---------- CSR build ----------
__global__ void zero_kernel() {
    int i = blockIdx.x * blockDim.x + threadIdx.x;
    if (i < N_NODES) { g_deg[i] = 0; g_cursor[i] = 0; }
}
__global__ void hist_kernel(const int* __restrict__ col) {
    int e = blockIdx.x * blockDim.x + threadIdx.x;
    if (e < N_EDGES) atomicAdd(&g_deg[col[e]], 1);
}
__global__ void scan_pass1() {
    __shared__ int sh[SCAN_CHUNK];
    int i = blockIdx.x * SCAN_CHUNK + threadIdx.x;
    sh[threadIdx.x] = (i < N_NODES) ? g_deg[i] : 0;
    __syncthreads();
    for (int off = SCAN_CHUNK / 2; off > 0; off >>= 1) {
        if (threadIdx.x < off) sh[threadIdx.x] += sh[threadIdx.x + off];
        __syncthreads();
    }
    if (threadIdx.x == 0) g_bsum[blockIdx.x] = sh[0];
}
__global__ void scan_pass2() {
    __shared__ int sh[256];
    int t = threadIdx.x;
    int v = (t < SCAN_NB) ? g_bsum[t] : 0;
    sh[t] = v;
    __syncthreads();
    for (int off = 1; off < 256; off <<= 1) {
        int add = (t >= off) ? sh[t - off] : 0;
        __syncthreads();
        sh[t] += add;
        __syncthreads();
    }
    if (t < SCAN_NB) g_bsum[t] = sh[t] - v;
    if (t == 255) g_off[N_NODES] = sh[255];
}
__global__ void scan_pass3() {
    __shared__ int sh[SCAN_CHUNK];
    int i = blockIdx.x * SCAN_CHUNK + threadIdx.x;
    int v = (i < N_NODES) ? g_deg[i] : 0;
    sh[threadIdx.x] = v;
    __syncthreads();
    for (int off = 1; off < SCAN_CHUNK; off <<= 1) {
        int t = (threadIdx.x >= off) ? sh[threadIdx.x - off] : 0;
        __syncthreads();
        sh[threadIdx.x] += t;
        __syncthreads();
    }
    if (i < N_NODES) {
        g_off[i]  = g_bsum[blockIdx.x] + sh[threadIdx.x] - v;
        g_dinv[i] = rsqrtf((float)(v + 1));
    }
}
__global__ void scatter_kernel(const int* __restrict__ row, const int* __restrict__ col) {
    int e = blockIdx.x * blockDim.x + threadIdx.x;
    if (e < N_EDGES) {
        int c = col[e];
        int pos = g_off[c] + atomicAdd(&g_cursor[c], 1);
        g_srow[pos] = row[e];
    }
}

// ---------- gather-aggregate; emits MMA A-fragments (m_hi,m_lo,x_hi,x_lo) ----------
// block = 512 threads = 16 node-warps = one 16-row fragment group
__global__ void __launch_bounds__(512, 2)
gather_kernel(const float* __restrict__ x) {
    extern __shared__ unsigned stage[];   // [v 4][q 8 padded 516]

    int tid  = threadIdx.x;
    int w    = tid >> 5;          // 0..15 = row within 16-group
    int lane = tid & 31;
    int node = blockIdx.x * 16 + w;

    const float4* x4 = (const float4*)x;
    float4 acc = make_float4(0.f, 0.f, 0.f, 0.f);
    int beg = g_off[node], end = g_off[node + 1];
    for (int e = beg; e < end; e++) {
        int r = g_srow[e];
        float wgt = g_dinv[r];
        float4 v = x4[r * 32 + lane];
        acc.x += wgt * v.x; acc.y += wgt * v.y; acc.z += wgt * v.z; acc.w += wgt * v.w;
    }
    float dc   = g_dinv[node];
    float degt = (float)(end - beg + 1);
    float sc   = dc / degt;
    float4 xc  = x4[node * 32 + lane];
    float m0 = (acc.x + dc * xc.x) * sc;
    float m1 = (acc.y + dc * xc.y) * sc;
    float m2 = (acc.z + dc * xc.z) * sc;
    float m3 = (acc.w + dc * xc.w) * sc;

    int gid = w & 7;
    int rh  = (w >> 3) & 1;   // 0 -> a0/a2 slots, 1 -> a1/a3 slots

    // pair 0: cols 4L,4L+1 ; pair 1: cols 4L+2,4L+3
#pragma unroll
    for (int p = 0; p < 2; p++) {
        int cp = 2 * lane + p;
        int q  = cp >> 3;
        int w8 = cp & 7;
        int tc = w8 & 3;
        int kh = w8 >> 2;
        int slot = kh * 2 + rh;
        int T = gid * 4 + tc;
        uint2 sm = (p == 0) ? split_bf2(m0, m1) : split_bf2(m2, m3);
        uint2 sx = (p == 0) ? split_bf2(xc.x, xc.y) : split_bf2(xc.z, xc.w);
        int base = q * GQ_PAD + T * 4 + slot;
        stage[0 * 8 * GQ_PAD + base] = sm.x;
        stage[1 * 8 * GQ_PAD + base] = sm.y;
        stage[2 * 8 * GQ_PAD + base] = sx.x;
        stage[3 * 8 * GQ_PAD + base] = sx.y;
    }
    __syncthreads();

    // copy out: [tile][q][mt][v][128 u32] coalesced
    int tile = (blockIdx.x * 16) >> 7;
    int mt   = ((blockIdx.x * 16) >> 4) & 7;
    unsigned* out32 = (unsigned*)g_afrag;
#pragma unroll
    for (int i = 0; i < 8; i++) {
        int lin = tid + i * 512;          // (v,q,j)
        int v = lin >> 10;
        int q = (lin >> 7) & 7;
        int j = lin & 127;
        unsigned val = stage[v * 8 * GQ_PAD + q * GQ_PAD + j];
        size_t gidx = ((((size_t)tile * 8 + q) * 8 + mt) * 4 + v) * 128 + j;
        out32[gidx] = val;
    }
}

// ---------- effective weights -> B-fragment images (hi/lo, msg/gate) ----------
__global__ void weff_kernel(const float* __restrict__ msg_W, const float* __restrict__ msg_A,
                            const float* __restrict__ msg_B,
                            const float* __restrict__ gate_W, const float* __restrict__ gate_A,
                            const float* __restrict__ gate_B) {
    int k = blockIdx.x;          // input feature 0..127
    int j = threadIdx.x;         // output feature 0..127
    __shared__ float sam[R], sag[R];
    if (j < R) { sam[j] = msg_A[j * H + k]; sag[j] = gate_A[j * H + k]; }
    __syncthreads();
    float am = 0.f, ag = 0.f;
#pragma unroll
    for (int r = 0; r < R; r++) {
        am += msg_B[j * R + r] * sam[r];
        ag += gate_B[j * R + r] * sag[r];
    }
    float wm = msg_W[j * H + k] + SCALING * am;
    float wg = gate_W[j * H + k] + SCALING * ag;

    int q  = k >> 4, k2 = k & 15;
    int nt = j >> 3, n  = j & 7;
    int T  = n * 4 + ((k2 & 7) >> 1);
    int reg = k2 >> 3, half = k2 & 1;
    int idx = ((((0) * 8 + q) * 16 + nt) * 32 + T) * 4 + reg * 2 + half;  // u16 within variant
    int vstride = 8 * 16 * 32 * 4;

    unsigned short* img = (unsigned short*)g_wfrag;
    __nv_bfloat16 mh = __float2bfloat16(wm);
    __nv_bfloat16 ml = __float2bfloat16(wm - __bfloat162float(mh));
    __nv_bfloat16 gh = __float2bfloat16(wg);
    __nv_bfloat16 gl = __float2bfloat16(wg - __bfloat162float(gh));
    img[0 * vstride + idx] = *(unsigned short*)&mh;
    img[1 * vstride + idx] = *(unsigned short*)&ml;
    img[2 * vstride + idx] = *(unsigned short*)&gh;
    img[3 * vstride + idx] = *(unsigned short*)&gl;
}

// ---------- fused: 2 GEMMs via HMMA + gate + residual + LN (persistent) ----------
__global__ void __launch_bounds__(FTHREADS, 1)
fused_kernel(const float* __restrict__ x,
             const float* __restrict__ msg_b, const float* __restrict__ gate_b,
             const float* __restrict__ ln_g, const float* __restrict__ ln_b,
             float* __restrict__ out) {
    extern __shared__ char smem[];
    unsigned* sB  = (unsigned*)smem;                 // 32768 u32
    float* s_mb = (float*)(smem + SMB_MB);
    float* s_gb = (float*)(smem + SMB_GB);
    float* s_ga = (float*)(smem + SMB_GA);
    float* s_be = (float*)(smem + SMB_BE);
    float* s1   = (float*)(smem + SMB_S1);           // [2][128]
    float* s2   = (float*)(smem + SMB_S2);

    int tid  = threadIdx.x;
    int wid  = tid >> 5, lane = tid & 31;
    int rg   = wid & 3;          // row group (32 rows)
    int cg   = wid >> 2;         // col group (64 cols)
    int gid  = lane >> 2;
    int tc   = lane & 3;

    // load B images + biases
    {
        const uint4* src = (const uint4*)g_wfrag;
        uint4* dst = (uint4*)sB;
#pragma unroll
        for (int i = 0; i < 32; i++) dst[tid + i * FTHREADS] = src[tid + i * FTHREADS];
        if (tid < 128) {
            s_mb[tid] = msg_b[tid];
            s_gb[tid] = gate_b[tid];
            s_ga[tid] = ln_g[tid];
            s_be[tid] = ln_b[tid];
        }
    }
    __syncthreads();

    for (int tile = blockIdx.x; tile < NT_TILES; tile += FGRID) {
        float acc_m[2][8][4], acc_g[2][8][4];
#pragma unroll
        for (int mt = 0; mt < 2; mt++)
#pragma unroll
            for (int nt = 0; nt < 8; nt++)
#pragma unroll
                for (int d = 0; d < 4; d++) { acc_m[mt][nt][d] = 0.f; acc_g[mt][nt][d] = 0.f; }

        for (int q = 0; q < 8; q++) {
            uint4 afr[2][4];   // [mt][v]
#pragma unroll
            for (int mt = 0; mt < 2; mt++) {
                int gmt = rg * 2 + mt;
                size_t base = (((size_t)tile * 8 + q) * 8 + gmt) * 4;
#pragma unroll
                for (int v = 0; v < 4; v++)
                    afr[mt][v] = g_afrag[(base + v) * 32 + lane];
            }
#pragma unroll
            for (int nt = 0; nt < 8; nt++) {
                int gnt = cg * 8 + nt;
                uint2 b_mh = *(const uint2*)(sB + (((0 * 8 + q) * 16 + gnt) * 32 + lane) * 2);
                uint2 b_ml = *(const uint2*)(sB + (((1 * 8 + q) * 16 + gnt) * 32 + lane) * 2);
                uint2 b_gh = *(const uint2*)(sB + (((2 * 8 + q) * 16 + gnt) * 32 + lane) * 2);
                uint2 b_gl = *(const uint2*)(sB + (((3 * 8 + q) * 16 + gnt) * 32 + lane) * 2);
#pragma unroll
                for (int mt = 0; mt < 2; mt++) {
                    mma16816(acc_m[mt][nt], (const unsigned*)&afr[mt][0], (const unsigned*)&b_mh);
                    mma16816(acc_m[mt][nt], (const unsigned*)&afr[mt][0], (const unsigned*)&b_ml);
                    mma16816(acc_m[mt][nt], (const unsigned*)&afr[mt][1], (const unsigned*)&b_mh);
                    mma16816(acc_g[mt][nt], (const unsigned*)&afr[mt][2], (const unsigned*)&b_gh);
                    mma16816(acc_g[mt][nt], (const unsigned*)&afr[mt][2], (const unsigned*)&b_gl);
                    mma16816(acc_g[mt][nt], (const unsigned*)&afr[mt][3], (const unsigned*)&b_gh);
                }
            }
        }

        // ---- epilogue ----
        int rowbase = tile * TILE_M + rg * 32;
        float sum1[4] = {0.f, 0.f, 0.f, 0.f};
        float sum2[4] = {0.f, 0.f, 0.f, 0.f};
#pragma unroll
        for (int mt = 0; mt < 2; mt++) {
            int r0 = rowbase + mt * 16 + gid;
            int r1 = r0 + 8;
#pragma unroll
            for (int nt = 0; nt < 8; nt++) {
                int c0 = cg * 64 + nt * 8 + 2 * tc;
                float2 h0 = make_float2(0.f, 0.f), h1 = make_float2(0.f, 0.f);
                if (r0 < N_NODES) h0 = *(const float2*)(x + (size_t)r0 * H + c0);
                if (r1 < N_NODES) h1 = *(const float2*)(x + (size_t)r1 * H + c0);
                float mb0 = s_mb[c0], mb1 = s_mb[c0 + 1];
                float gb0 = s_gb[c0], gb1 = s_gb[c0 + 1];
                float* am = acc_m[mt][nt];
                float* ag = acc_g[mt][nt];
                float v0 = h0.x + (am[0] + mb0) / (1.f + __expf(-(ag[0] + gb0)));
                float v1 = h0.y + (am[1] + mb1) / (1.f + __expf(-(ag[1] + gb1)));
                float v2 = h1.x + (am[2] + mb0) / (1.f + __expf(-(ag[2] + gb0)));
                float v3 = h1.y + (am[3] + mb1) / (1.f + __expf(-(ag[3] + gb1)));
                am[0] = v0; am[1] = v1; am[2] = v2; am[3] = v3;
                sum1[mt * 2]     += v0 + v1;  sum2[mt * 2]     += v0 * v0 + v1 * v1;
                sum1[mt * 2 + 1] += v2 + v3;  sum2[mt * 2 + 1] += v2 * v2 + v3 * v3;
            }
        }
        // quad reduce (lanes sharing gid)
#pragma unroll
        for (int i = 0; i < 4; i++) {
            sum1[i] += __shfl_xor_sync(0xffffffffu, sum1[i], 1);
            sum1[i] += __shfl_xor_sync(0xffffffffu, sum1[i], 2);
            sum2[i] += __shfl_xor_sync(0xffffffffu, sum2[i], 1);
            sum2[i] += __shfl_xor_sync(0xffffffffu, sum2[i], 2);
        }
        if (tc == 0) {
#pragma unroll
            for (int i = 0; i < 4; i++) {
                int rl = rg * 32 + (i >> 1) * 16 + gid + (i & 1) * 8;
                s1[cg * 128 + rl] = sum1[i];
                s2[cg * 128 + rl] = sum2[i];
            }
        }
        __syncthreads();

        float mu_[4], ri_[4];
#pragma unroll
        for (int i = 0; i < 4; i++) {
            int rl = rg * 32 + (i >> 1) * 16 + gid + (i & 1) * 8;
            float S  = s1[rl] + s1[128 + rl];
            float S2 = s2[rl] + s2[128 + rl];
            float mu = S * (1.f / (float)H);
            float var = S2 * (1.f / (float)H) - mu * mu;
            mu_[i] = mu;
            ri_[i] = rsqrtf(var + LN_EPS);
        }
#pragma unroll
        for (int mt = 0; mt < 2; mt++) {
            int r0 = rowbase + mt * 16 + gid;
            int r1 = r0 + 8;
#pragma unroll
            for (int nt = 0; nt < 8; nt++) {
                int c0 = cg * 64 + nt * 8 + 2 * tc;
                float ga0 = s_ga[c0], ga1 = s_ga[c0 + 1];
                float be0 = s_be[c0], be1 = s_be[c0 + 1];
                float* am = acc_m[mt][nt];
                if (r0 < N_NODES) {
                    float2 o;
                    o.x = (am[0] - mu_[mt * 2]) * ri_[mt * 2] * ga0 + be0;
                    o.y = (am[1] - mu_[mt * 2]) * ri_[mt * 2] * ga1 + be1;
                    *(float2*)(out + (size_t)r0 * H + c0) = o;
                }
                if (r1 < N_NODES) {
                    float2 o;
                    o.x = (am[2] - mu_[mt * 2 + 1]) * ri_[mt * 2 + 1] * ga0 + be0;
                    o.y = (am[3] - mu_[mt * 2 + 1]) * ri_[mt * 2 + 1] * ga1 + be1;
                    *(float2*)(out + (size_t)r1 * H + c0) = o;
                }
            }
        }
        __syncthreads();   // s1/s2 reuse safety
    }
}

// ---------- launch ----------
extern "C" void kernel_launch(void* const* d_in, const int* in_sizes, int n_in,
                              void* d_out, int out_size) {
    const float* x      = (const float*)d_in[0];
    const int*   ei     = (const int*)d_in[1];
    const float* msg_W  = (const float*)d_in[2];
    const float* msg_b  = (const float*)d_in[3];
    const float* msg_A  = (const float*)d_in[4];
    const float* msg_B  = (const float*)d_in[5];
    const float* gate_W = (const float*)d_in[6];
    const float* gate_b = (const float*)d_in[7];
    const float* gate_A = (const float*)d_in[8];
    const float* gate_B = (const float*)d_in[9];
    const float* ln_g   = (const float*)d_in[10];
    const float* ln_b   = (const float*)d_in[11];
    float* out = (float*)d_out;

    const int* rows = ei;
    const int* cols = ei + N_EDGES;

    zero_kernel<<<(N_NODES + 255) / 256, 256>>>();
    hist_kernel<<<(N_EDGES + 255) / 256, 256>>>(cols);
    scan_pass1<<<SCAN_NB, SCAN_CHUNK>>>();
    scan_pass2<<<1, 256>>>();
    scan_pass3<<<SCAN_NB, SCAN_CHUNK>>>();
    scatter_kernel<<<(N_EDGES + 255) / 256, 256>>>(rows, cols);

    cudaFuncSetAttribute(gather_kernel, cudaFuncAttributeMaxDynamicSharedMemorySize, GATHER_SMEM);
    gather_kernel<<<N_NODES / 16, 512, GATHER_SMEM>>>(x);

    weff_kernel<<<H, H>>>(msg_W, msg_A, msg_B, gate_W, gate_A, gate_B);

    cudaFuncSetAttribute(fused_kernel, cudaFuncAttributeMaxDynamicSharedMemorySize, FUSED_SMEM);
    fused_kernel<<<FGRID, FTHREADS, FUSED_SMEM>>>(x, msg_b, gate_b, ln_g, ln_b, out);
}

// round 6
// speedup vs baseline: 1.3459x; 1.0768x over previous
#include <cuda_runtime.h>
#include <cuda_bf16.h>
#include <math.h>
#include <stdint.h>

#define N_NODES 100000
#define N_EDGES 600000
#define H 128
#define R 16
#define SCALING 2.0f
#define LN_EPS 1e-5f

#define SCAN_CHUNK 512
#define SCAN_NB ((N_NODES + SCAN_CHUNK - 1) / SCAN_CHUNK)   // 196

#define TILE_M 128
#define NT_TILES ((N_NODES + TILE_M - 1) / TILE_M)          // 782
#define FGRID 148
#define FTHREADS 512

// fused smem layout (bytes)
#define SMB_W    0                    // B-fragment images 128KB
#define SMB_STG  131072               // A staging 66048
#define SMB_MB   197120
#define SMB_GB   197632
#define SMB_GA   198144
#define SMB_BE   198656
#define SMB_S1   199168               // [8][64] f32
#define SMB_S2   201216
#define FUSED_SMEM 203264

#define QPAD 516                      // words per (v,q) staging plane (4*128 + 4 pad)

// ---------- static device scratch ----------
__device__ int   g_deg[N_NODES];
__device__ int   g_off[N_NODES + 1];
__device__ float g_dinv[N_NODES];
__device__ int   g_srow[N_EDGES];
__device__ int   g_bsum[256];
// B fragments: [v 4][q 8][nt 16][T 32][b0,b1] u32 = 128 KB
__device__ unsigned g_wfrag[4 * 8 * 16 * 32 * 2];

// ---------- helpers ----------
__device__ __forceinline__ unsigned pack_bf2(float e0, float e1) {
    unsigned r;
    asm("cvt.rn.bf16x2.f32 %0, %1, %2;" : "=r"(r) : "f"(e1), "f"(e0));  // lo=e0, hi=e1
    return r;
}
__device__ __forceinline__ uint2 split_bf2(float e0, float e1) {
    unsigned hi = pack_bf2(e0, e1);
    float h0 = __uint_as_float(hi << 16);
    float h1 = __uint_as_float(hi & 0xffff0000u);
    unsigned lo = pack_bf2(e0 - h0, e1 - h1);
    return make_uint2(hi, lo);
}
__device__ __forceinline__ void mma16816(float* d, const unsigned* a, const unsigned* b) {
    asm volatile(
        "mma.sync.aligned.m16n8k16.row.col.f32.bf16.bf16.f32 "
        "{%0,%1,%2,%3}, {%4,%5,%6,%7}, {%8,%9}, {%0,%1,%2,%3};"
        : "+f"(d[0]), "+f"(d[1]), "+f"(d[2]), "+f"(d[3])
        : "r"(a[0]), "r"(a[1]), "r"(a[2]), "r"(a[3]), "r"(b[0]), "r"(b[1]));
}
__device__ __forceinline__ int stg_i(int v, int q, int g, int tw) {
    return (v * 8 + q) * QPAD + g * 128 + tw;
}

// ---------- CSR build ----------
__global__ void zero_kernel() {
    int i = blockIdx.x * blockDim.x + threadIdx.x;
    if (i < N_NODES) g_deg[i] = 0;
}
__global__ void hist_kernel(const int* __restrict__ col) {
    int e = blockIdx.x * blockDim.x + threadIdx.x;
    if (e < N_EDGES) atomicAdd(&g_deg[col[e]], 1);
}
__global__ void scan_pass1() {
    __shared__ int sh[SCAN_CHUNK];
    int i = blockIdx.x * SCAN_CHUNK + threadIdx.x;
    sh[threadIdx.x] = (i < N_NODES) ? g_deg[i] : 0;
    __syncthreads();
    for (int off = SCAN_CHUNK / 2; off > 0; off >>= 1) {
        if (threadIdx.x < off) sh[threadIdx.x] += sh[threadIdx.x + off];
        __syncthreads();
    }
    if (threadIdx.x == 0) g_bsum[blockIdx.x] = sh[0];
}
__global__ void scan_pass2() {
    __shared__ int sh[256];
    int t = threadIdx.x;
    int v = (t < SCAN_NB) ? g_bsum[t] : 0;
    sh[t] = v;
    __syncthreads();
    for (int off = 1; off < 256; off <<= 1) {
        int add = (t >= off) ? sh[t - off] : 0;
        __syncthreads();
        sh[t] += add;
        __syncthreads();
    }
    if (t < SCAN_NB) g_bsum[t] = sh[t] - v;
    if (t == 255) g_off[N_NODES] = sh[255];
}
__global__ void scan_pass3() {
    __shared__ int sh[SCAN_CHUNK];
    int i = blockIdx.x * SCAN_CHUNK + threadIdx.x;
    int v = (i < N_NODES) ? g_deg[i] : 0;
    sh[threadIdx.x] = v;
    __syncthreads();
    for (int off = 1; off < SCAN_CHUNK; off <<= 1) {
        int t = (threadIdx.x >= off) ? sh[threadIdx.x - off] : 0;
        __syncthreads();
        sh[threadIdx.x] += t;
        __syncthreads();
    }
    if (i < N_NODES) {
        g_off[i]  = g_bsum[blockIdx.x] + sh[threadIdx.x] - v;
        g_dinv[i] = rsqrtf((float)(v + 1));
    }
}
// claims slots by decrementing g_deg (deg is dead after scan_pass3 computed dinv)
__global__ void scatter_kernel(const int* __restrict__ row, const int* __restrict__ col) {
    int e = blockIdx.x * blockDim.x + threadIdx.x;
    if (e < N_EDGES) {
        int c = col[e];
        int p = atomicAdd(&g_deg[c], -1) - 1;
        g_srow[g_off[c] + p] = row[e];
    }
}

// ---------- effective weights -> B-fragment images (hi/lo, msg/gate) ----------
__global__ void weff_kernel(const float* __restrict__ msg_W, const float* __restrict__ msg_A,
                            const float* __restrict__ msg_B,
                            const float* __restrict__ gate_W, const float* __restrict__ gate_A,
                            const float* __restrict__ gate_B) {
    int k = blockIdx.x;          // input feature 0..127
    int j = threadIdx.x;         // output feature 0..127
    __shared__ float sam[R], sag[R];
    if (j < R) { sam[j] = msg_A[j * H + k]; sag[j] = gate_A[j * H + k]; }
    __syncthreads();
    float am = 0.f, ag = 0.f;
#pragma unroll
    for (int r = 0; r < R; r++) {
        am += msg_B[j * R + r] * sam[r];
        ag += gate_B[j * R + r] * sag[r];
    }
    float wm = msg_W[j * H + k] + SCALING * am;
    float wg = gate_W[j * H + k] + SCALING * ag;

    int q  = k >> 4, k2 = k & 15;
    int nt = j >> 3, n  = j & 7;
    int T  = n * 4 + ((k2 & 7) >> 1);
    int reg = k2 >> 3, half = k2 & 1;
    int idx = ((q * 16 + nt) * 32 + T) * 4 + reg * 2 + half;  // u16 within variant
    int vstride = 8 * 16 * 32 * 4;

    unsigned short* img = (unsigned short*)g_wfrag;
    __nv_bfloat16 mh = __float2bfloat16(wm);
    __nv_bfloat16 ml = __float2bfloat16(wm - __bfloat162float(mh));
    __nv_bfloat16 gh = __float2bfloat16(wg);
    __nv_bfloat16 gl = __float2bfloat16(wg - __bfloat162float(gh));
    img[0 * vstride + idx] = *(unsigned short*)&mh;
    img[1 * vstride + idx] = *(unsigned short*)&ml;
    img[2 * vstride + idx] = *(unsigned short*)&gh;
    img[3 * vstride + idx] = *(unsigned short*)&gl;
}

// ---------- persistent fused: gather + 2 HMMA GEMMs + gate + residual + LN ----------
__global__ void __launch_bounds__(FTHREADS, 1)
fused_kernel(const float* __restrict__ x,
             const float* __restrict__ msg_b, const float* __restrict__ gate_b,
             const float* __restrict__ ln_g, const float* __restrict__ ln_b,
             float* __restrict__ out) {
    extern __shared__ char smem[];
    unsigned* sB   = (unsigned*)smem;                  // B frags
    unsigned* stg  = (unsigned*)(smem + SMB_STG);      // A staging
    float* s_mb = (float*)(smem + SMB_MB);
    float* s_gb = (float*)(smem + SMB_GB);
    float* s_ga = (float*)(smem + SMB_GA);
    float* s_be = (float*)(smem + SMB_BE);
    float* s1   = (float*)(smem + SMB_S1);             // [8][64]
    float* s2   = (float*)(smem + SMB_S2);

    int tid  = threadIdx.x;
    int w    = tid >> 5, lane = tid & 31;
    int cg   = w >> 1;            // col group (16 cols)
    int rg   = w & 1;             // row group (32 rows of the 64-row half)
    int gid  = lane >> 2;
    int tc4  = lane & 3;

    // load B images + biases (once)
    {
        const uint4* src = (const uint4*)g_wfrag;
        uint4* dst = (uint4*)sB;
#pragma unroll
        for (int i = 0; i < 16; i++) dst[tid + i * FTHREADS] = src[tid + i * FTHREADS];
        if (tid < 128) {
            s_mb[tid] = msg_b[tid];
            s_gb[tid] = gate_b[tid];
            s_ga[tid] = ln_g[tid];
            s_be[tid] = ln_b[tid];
        }
    }
    __syncthreads();

    const float4* x4 = (const float4*)x;

    for (int tile = blockIdx.x; tile < NT_TILES; tile += FGRID) {
#pragma unroll 1
        for (int half = 0; half < 2; half++) {
            int base = tile * TILE_M + half * 64;

            // ---- gather 4 nodes per warp, stage A-fragments ----
#pragma unroll 1
            for (int i = 0; i < 4; i++) {
                int r_loc = w * 4 + i;          // 0..63
                int node  = base + r_loc;
                float4 xc = make_float4(0.f, 0.f, 0.f, 0.f);
                float m0 = 0.f, m1 = 0.f, m2 = 0.f, m3 = 0.f;
                if (node < N_NODES) {
                    float4 acc = make_float4(0.f, 0.f, 0.f, 0.f);
                    int beg = g_off[node], end = g_off[node + 1];
                    for (int e = beg; e < end; e++) {
                        int r = g_srow[e];
                        float wgt = g_dinv[r];
                        float4 v = x4[r * 32 + lane];
                        acc.x += wgt * v.x; acc.y += wgt * v.y;
                        acc.z += wgt * v.z; acc.w += wgt * v.w;
                    }
                    float dc = g_dinv[node];
                    float sc = dc / (float)(end - beg + 1);
                    xc = x4[node * 32 + lane];
                    m0 = (acc.x + dc * xc.x) * sc;
                    m1 = (acc.y + dc * xc.y) * sc;
                    m2 = (acc.z + dc * xc.z) * sc;
                    m3 = (acc.w + dc * xc.w) * sc;
                }
                int g   = r_loc >> 4;
                int w16 = r_loc & 15;
                int gd  = w16 & 7;
                int rh  = w16 >> 3;
#pragma unroll
                for (int p = 0; p < 2; p++) {
                    int cp = 2 * lane + p;
                    int q  = cp >> 3;
                    int w8 = cp & 7;
                    int tcc = w8 & 3;
                    int kh  = w8 >> 2;
                    int tw = (gd * 4 + tcc) * 4 + kh * 2 + rh;
                    uint2 sm = (p == 0) ? split_bf2(m0, m1) : split_bf2(m2, m3);
                    uint2 sx = (p == 0) ? split_bf2(xc.x, xc.y) : split_bf2(xc.z, xc.w);
                    stg[stg_i(0, q, g, tw)] = sm.x;
                    stg[stg_i(1, q, g, tw)] = sm.y;
                    stg[stg_i(2, q, g, tw)] = sx.x;
                    stg[stg_i(3, q, g, tw)] = sx.y;
                }
            }
            __syncthreads();

            // ---- MMA: 64 x 128 x 128 for msg & gate (3-term bf16 split) ----
            float acc_m[2][2][4], acc_g[2][2][4];
#pragma unroll
            for (int mt = 0; mt < 2; mt++)
#pragma unroll
                for (int nt = 0; nt < 2; nt++)
#pragma unroll
                    for (int d = 0; d < 4; d++) { acc_m[mt][nt][d] = 0.f; acc_g[mt][nt][d] = 0.f; }

#pragma unroll 1
            for (int q = 0; q < 8; q++) {
                uint4 afr[2][4];
#pragma unroll
                for (int mt = 0; mt < 2; mt++)
#pragma unroll
                    for (int v = 0; v < 4; v++)
                        afr[mt][v] = *(const uint4*)&stg[stg_i(v, q, rg * 2 + mt, lane * 4)];
#pragma unroll
                for (int nt = 0; nt < 2; nt++) {
                    int gnt = cg * 2 + nt;
                    uint2 bmh = *(const uint2*)(sB + (((0 * 8 + q) * 16 + gnt) * 32 + lane) * 2);
                    uint2 bml = *(const uint2*)(sB + (((1 * 8 + q) * 16 + gnt) * 32 + lane) * 2);
                    uint2 bgh = *(const uint2*)(sB + (((2 * 8 + q) * 16 + gnt) * 32 + lane) * 2);
                    uint2 bgl = *(const uint2*)(sB + (((3 * 8 + q) * 16 + gnt) * 32 + lane) * 2);
#pragma unroll
                    for (int mt = 0; mt < 2; mt++) {
                        mma16816(acc_m[mt][nt], (const unsigned*)&afr[mt][0], (const unsigned*)&bmh);
                        mma16816(acc_m[mt][nt], (const unsigned*)&afr[mt][0], (const unsigned*)&bml);
                        mma16816(acc_m[mt][nt], (const unsigned*)&afr[mt][1], (const unsigned*)&bmh);
                        mma16816(acc_g[mt][nt], (const unsigned*)&afr[mt][2], (const unsigned*)&bgh);
                        mma16816(acc_g[mt][nt], (const unsigned*)&afr[mt][2], (const unsigned*)&bgl);
                        mma16816(acc_g[mt][nt], (const unsigned*)&afr[mt][3], (const unsigned*)&bgh);
                    }
                }
            }

            // ---- epilogue: gate + residual, partial LN sums ----
            int rowbase = base + rg * 32;
            float sum1[2][2] = {{0.f, 0.f}, {0.f, 0.f}};   // [mt][rhh]
            float sum2[2][2] = {{0.f, 0.f}, {0.f, 0.f}};
#pragma unroll
            for (int mt = 0; mt < 2; mt++) {
                int r0 = rowbase + mt * 16 + gid;
                int r1 = r0 + 8;
#pragma unroll
                for (int nt = 0; nt < 2; nt++) {
                    int c0 = cg * 16 + nt * 8 + 2 * tc4;
                    float2 h0 = make_float2(0.f, 0.f), h1 = make_float2(0.f, 0.f);
                    if (r0 < N_NODES) h0 = *(const float2*)(x + (size_t)r0 * H + c0);
                    if (r1 < N_NODES) h1 = *(const float2*)(x + (size_t)r1 * H + c0);
                    float mb0 = s_mb[c0], mb1 = s_mb[c0 + 1];
                    float gb0 = s_gb[c0], gb1 = s_gb[c0 + 1];
                    float* am = acc_m[mt][nt];
                    float* ag = acc_g[mt][nt];
                    float v0 = h0.x + (am[0] + mb0) / (1.f + __expf(-(ag[0] + gb0)));
                    float v1 = h0.y + (am[1] + mb1) / (1.f + __expf(-(ag[1] + gb1)));
                    float v2 = h1.x + (am[2] + mb0) / (1.f + __expf(-(ag[2] + gb0)));
                    float v3 = h1.y + (am[3] + mb1) / (1.f + __expf(-(ag[3] + gb1)));
                    am[0] = v0; am[1] = v1; am[2] = v2; am[3] = v3;
                    sum1[mt][0] += v0 + v1;  sum2[mt][0] += v0 * v0 + v1 * v1;
                    sum1[mt][1] += v2 + v3;  sum2[mt][1] += v2 * v2 + v3 * v3;
                }
            }
#pragma unroll
            for (int mt = 0; mt < 2; mt++)
#pragma unroll
                for (int rr = 0; rr < 2; rr++) {
                    sum1[mt][rr] += __shfl_xor_sync(0xffffffffu, sum1[mt][rr], 1);
                    sum1[mt][rr] += __shfl_xor_sync(0xffffffffu, sum1[mt][rr], 2);
                    sum2[mt][rr] += __shfl_xor_sync(0xffffffffu, sum2[mt][rr], 1);
                    sum2[mt][rr] += __shfl_xor_sync(0xffffffffu, sum2[mt][rr], 2);
                }
            if (tc4 == 0) {
#pragma unroll
                for (int mt = 0; mt < 2; mt++)
#pragma unroll
                    for (int rr = 0; rr < 2; rr++) {
                        int rl = rg * 32 + mt * 16 + gid + rr * 8;
                        s1[cg * 64 + rl] = sum1[mt][rr];
                        s2[cg * 64 + rl] = sum2[mt][rr];
                    }
            }
            __syncthreads();

            // ---- LN finalize + store ----
            float mu_[2][2], ri_[2][2];
#pragma unroll
            for (int mt = 0; mt < 2; mt++)
#pragma unroll
                for (int rr = 0; rr < 2; rr++) {
                    int rl = rg * 32 + mt * 16 + gid + rr * 8;
                    float S = 0.f, S2 = 0.f;
#pragma unroll
                    for (int c = 0; c < 8; c++) { S += s1[c * 64 + rl]; S2 += s2[c * 64 + rl]; }
                    float mu = S * (1.f / (float)H);
                    float var = S2 * (1.f / (float)H) - mu * mu;
                    mu_[mt][rr] = mu;
                    ri_[mt][rr] = rsqrtf(var + LN_EPS);
                }
#pragma unroll
            for (int mt = 0; mt < 2; mt++) {
                int r0 = rowbase + mt * 16 + gid;
                int r1 = r0 + 8;
#pragma unroll
                for (int nt = 0; nt < 2; nt++) {
                    int c0 = cg * 16 + nt * 8 + 2 * tc4;
                    float ga0 = s_ga[c0], ga1 = s_ga[c0 + 1];
                    float be0 = s_be[c0], be1 = s_be[c0 + 1];
                    float* am = acc_m[mt][nt];
                    if (r0 < N_NODES) {
                        float2 o;
                        o.x = (am[0] - mu_[mt][0]) * ri_[mt][0] * ga0 + be0;
                        o.y = (am[1] - mu_[mt][0]) * ri_[mt][0] * ga1 + be1;
                        *(float2*)(out + (size_t)r0 * H + c0) = o;
                    }
                    if (r1 < N_NODES) {
                        float2 o;
                        o.x = (am[2] - mu_[mt][1]) * ri_[mt][1] * ga0 + be0;
                        o.y = (am[3] - mu_[mt][1]) * ri_[mt][1] * ga1 + be1;
                        *(float2*)(out + (size_t)r1 * H + c0) = o;
                    }
                }
            }
            __syncthreads();   // staging + partials reuse safety
        }
    }
}

// ---------- launch ----------
extern "C" void kernel_launch(void* const* d_in, const int* in_sizes, int n_in,
                              void* d_out, int out_size) {
    const float* x      = (const float*)d_in[0];
    const int*   ei     = (const int*)d_in[1];
    const float* msg_W  = (const float*)d_in[2];
    const float* msg_b  = (const float*)d_in[3];
    const float* msg_A  = (const float*)d_in[4];
    const float* msg_B  = (const float*)d_in[5];
    const float* gate_W = (const float*)d_in[6];
    const float* gate_b = (const float*)d_in[7];
    const float* gate_A = (const float*)d_in[8];
    const float* gate_B = (const float*)d_in[9];
    const float* ln_g   = (const float*)d_in[10];
    const float* ln_b   = (const float*)d_in[11];
    float* out = (float*)d_out;

    const int* rows = ei;
    const int* cols = ei + N_EDGES;

    zero_kernel<<<(N_NODES + 255) / 256, 256>>>();
    hist_kernel<<<(N_EDGES + 255) / 256, 256>>>(cols);
    scan_pass1<<<SCAN_NB, SCAN_CHUNK>>>();
    scan_pass2<<<1, 256>>>();
    scan_pass3<<<SCAN_NB, SCAN_CHUNK>>>();
    scatter_kernel<<<(N_EDGES + 255) / 256, 256>>>(rows, cols);
    weff_kernel<<<H, H>>>(msg_W, msg_A, msg_B, gate_W, gate_A, gate_B);

    cudaFuncSetAttribute(fused_kernel, cudaFuncAttributeMaxDynamicSharedMemorySize, FUSED_SMEM);
    fused_kernel<<<FGRID, FTHREADS, FUSED_SMEM>>>(x, msg_b, gate_b, ln_g, ln_b, out);
}